// round 2
// baseline (speedup 1.0000x reference)
#include <cuda_runtime.h>

// Problem dims (fixed per reference)
#define NN   20000
#define EE   40000
#define FAx  75
#define FBx  12
#define CCx  100
#define GGx  1000
#define EPSV 1e-5f

#define TBE 16   // edges per block in the edge kernel

// Scratch (static device arrays: no allocation allowed)
__device__ float g_h[NN * CCx];        // node features h [N, C]
__device__ float g_pooled[GGx * CCx];  // per-molecule pooled [G, C]
__device__ float g_stats[2 * CCx];     // [sum, sumsq] per channel

// ---------------------------------------------------------------------------
// K0: zero the accumulators that are atomically built each launch
// ---------------------------------------------------------------------------
__global__ void k_zero() {
    int idx = blockIdx.x * blockDim.x + threadIdx.x;
    int stride = gridDim.x * blockDim.x;
    int tot = GGx * CCx + 2 * CCx;
    for (int i = idx; i < tot; i += stride) {
        if (i < GGx * CCx) g_pooled[i] = 0.f;
        else               g_stats[i - GGx * CCx] = 0.f;
    }
}

// ---------------------------------------------------------------------------
// K1: h[n,c] = x[n,:] @ W_root[:,c] + bias[c]   (one block per node)
// ---------------------------------------------------------------------------
__global__ void k_root(const float* __restrict__ x,
                       const float* __restrict__ Wr,
                       const float* __restrict__ bias) {
    __shared__ float xs[FAx];
    int n = blockIdx.x;
    int tid = threadIdx.x;
    if (tid < FAx) xs[tid] = x[n * FAx + tid];
    __syncthreads();
    if (tid < CCx) {
        float acc = bias[tid];
#pragma unroll
        for (int i = 0; i < FAx; i++)
            acc = fmaf(xs[i], Wr[i * CCx + tid], acc);
        g_h[n * CCx + tid] = acc;
    }
}

// ---------------------------------------------------------------------------
// K2: fused NNConv edge kernel.
//   For each edge e: t[i,c] = b1[i*C+c] + sum_j ea[e,j]*W1[j, i*C+c]
//                    msg[e,c] += x[src[e], i] * relu(t[i,c])
//   atomicAdd msg into g_h[dst[e], c].
// 128 threads = 32 c-lanes x 4 e-groups; each thread owns a 4(edge) x 4(chan)
// register tile -> inner j loop is 16 FFMA per 4 LDS + 4 LDG.
// ---------------------------------------------------------------------------
__global__ void __launch_bounds__(128, 8)
k_edge(const float* __restrict__ x,
       const float* __restrict__ ea,
       const float* __restrict__ W1,
       const float* __restrict__ b1,
       const int*   __restrict__ eidx) {
    __shared__ float ea_s[TBE][FBx];
    __shared__ float xs_s[TBE][FAx + 1];
    __shared__ int   dst_s[TBE];

    const int tid = threadIdx.x;
    const int e0  = blockIdx.x * TBE;

    // stage edge attrs
    for (int idx = tid; idx < TBE * FBx; idx += 128) {
        int e = idx / FBx, j = idx % FBx;
        ea_s[e][j] = ea[(e0 + e) * FBx + j];
    }
    if (tid < TBE) dst_s[tid] = eidx[EE + e0 + tid];
    // stage source-node features (rows contiguous -> mostly coalesced)
    for (int idx = tid; idx < TBE * FAx; idx += 128) {
        int e = idx / FAx, i = idx % FAx;
        int s = eidx[e0 + e];           // L1-hit after first touch per e
        xs_s[e][i] = x[s * FAx + i];
    }
    __syncthreads();

    const int tidc = tid & 31;   // c lane
    const int tide = tid >> 5;   // edge group (0..3), 4 edges each

    // channel indices handled by this thread (clamped to stay in-bounds;
    // invalid ones masked at the epilogue)
    int ck[4];
    bool cok[4];
#pragma unroll
    for (int k = 0; k < 4; k++) {
        int c = tidc + 32 * k;
        cok[k] = (c < CCx);
        ck[k]  = cok[k] ? c : (CCx - 1);
    }

    float acc[4][4];   // [edge][chan]
#pragma unroll
    for (int e = 0; e < 4; e++)
#pragma unroll
        for (int k = 0; k < 4; k++) acc[e][k] = 0.f;

    for (int i = 0; i < FAx; i++) {
        const int colbase = i * CCx;
        float bv[4];
#pragma unroll
        for (int k = 0; k < 4; k++) bv[k] = b1[colbase + ck[k]];

        float t[4][4];
#pragma unroll
        for (int e = 0; e < 4; e++)
#pragma unroll
            for (int k = 0; k < 4; k++) t[e][k] = bv[k];

#pragma unroll
        for (int j = 0; j < FBx; j++) {
            float wv[4];
#pragma unroll
            for (int k = 0; k < 4; k++)
                wv[k] = W1[j * (FAx * CCx) + colbase + ck[k]];
            float av[4];
#pragma unroll
            for (int e = 0; e < 4; e++)
                av[e] = ea_s[tide * 4 + e][j];        // smem broadcast
#pragma unroll
            for (int e = 0; e < 4; e++)
#pragma unroll
                for (int k = 0; k < 4; k++)
                    t[e][k] = fmaf(av[e], wv[k], t[e][k]);
        }

        float xv[4];
#pragma unroll
        for (int e = 0; e < 4; e++)
            xv[e] = xs_s[tide * 4 + e][i];            // smem broadcast
#pragma unroll
        for (int e = 0; e < 4; e++)
#pragma unroll
            for (int k = 0; k < 4; k++)
                acc[e][k] = fmaf(xv[e], fmaxf(t[e][k], 0.f), acc[e][k]);
    }

    // scatter-add messages into destination nodes
#pragma unroll
    for (int e = 0; e < 4; e++) {
        int d = dst_s[tide * 4 + e];
        float* hrow = &g_h[d * CCx];
#pragma unroll
        for (int k = 0; k < 4; k++)
            if (cok[k]) atomicAdd(&hrow[tidc + 32 * k], acc[e][k]);
    }
}

// ---------------------------------------------------------------------------
// K3: relu in place + per-channel sum & sumsq (for BatchNorm batch stats)
// ---------------------------------------------------------------------------
__global__ void k_stats() {
    __shared__ float s1[CCx], s2[CCx];
    int tid = threadIdx.x;
    if (tid < CCx) { s1[tid] = 0.f; s2[tid] = 0.f; }
    __syncthreads();
    int stride = gridDim.x * blockDim.x;
    for (int idx = blockIdx.x * blockDim.x + tid; idx < NN * CCx; idx += stride) {
        float r = fmaxf(g_h[idx], 0.f);
        g_h[idx] = r;                         // fold relu here
        int c = idx % CCx;
        atomicAdd(&s1[c], r);
        atomicAdd(&s2[c], r * r);
    }
    __syncthreads();
    if (tid < CCx) {
        atomicAdd(&g_stats[tid],        s1[tid]);
        atomicAdd(&g_stats[CCx + tid],  s2[tid]);
    }
}

// ---------------------------------------------------------------------------
// K4: batchnorm-apply + global_add_pool (scatter by molecule)
// ---------------------------------------------------------------------------
__global__ void k_normpool(const float* __restrict__ gamma,
                           const float* __restrict__ beta,
                           const int*   __restrict__ batch) {
    __shared__ float sm[CCx], sv[CCx], sg[CCx], sb[CCx];
    int tid = threadIdx.x;
    if (tid < CCx) {
        float m   = g_stats[tid] * (1.f / NN);
        float var = g_stats[CCx + tid] * (1.f / NN) - m * m;
        sm[tid] = m;
        sv[tid] = rsqrtf(var + EPSV);
        sg[tid] = gamma[tid];
        sb[tid] = beta[tid];
    }
    __syncthreads();
    int stride = gridDim.x * blockDim.x;
    for (int idx = blockIdx.x * blockDim.x + tid; idx < NN * CCx; idx += stride) {
        int c = idx % CCx;
        int n = idx / CCx;
        float hn = fmaf(sg[c] * (g_h[idx] - sm[c]), sv[c], sb[c]);
        atomicAdd(&g_pooled[batch[n] * CCx + c], hn);
    }
}

// ---------------------------------------------------------------------------
// K5: out[g] = relu(pooled[g,:]) @ W_out + b_out     (one warp per molecule)
// ---------------------------------------------------------------------------
__global__ void k_out(const float* __restrict__ Wout,
                      const float* __restrict__ bout,
                      float* __restrict__ out) {
    int g = blockIdx.x * (blockDim.x >> 5) + (threadIdx.x >> 5);
    int lane = threadIdx.x & 31;
    if (g >= GGx) return;
    float acc = 0.f;
    for (int c = lane; c < CCx; c += 32)
        acc = fmaf(fmaxf(g_pooled[g * CCx + c], 0.f), Wout[c], acc);
#pragma unroll
    for (int o = 16; o; o >>= 1)
        acc += __shfl_xor_sync(0xffffffff, acc, o);
    if (lane == 0) out[g] = acc + bout[0];
}

// ---------------------------------------------------------------------------
extern "C" void kernel_launch(void* const* d_in, const int* in_sizes, int n_in,
                              void* d_out, int out_size) {
    const float* x     = (const float*)d_in[0];   // [N, FA]
    const float* ea    = (const float*)d_in[1];   // [E, FB]
    const float* W1    = (const float*)d_in[2];   // [FB, FA*C]
    const float* b1    = (const float*)d_in[3];   // [FA*C]
    const float* Wr    = (const float*)d_in[4];   // [FA, C]
    const float* bias  = (const float*)d_in[5];   // [C]
    const float* gamma = (const float*)d_in[6];   // [C]
    const float* beta  = (const float*)d_in[7];   // [C]
    const float* Wout  = (const float*)d_in[8];   // [C, 1]
    const float* bout  = (const float*)d_in[9];   // [1]
    const int*   eidx  = (const int*)d_in[10];    // [2, E]
    const int*   batch = (const int*)d_in[11];    // [N]
    float* out = (float*)d_out;                   // [G, 1]

    k_zero<<<128, 256>>>();
    k_root<<<NN, 128>>>(x, Wr, bias);
    k_edge<<<EE / TBE, 128>>>(x, ea, W1, b1, eidx);
    k_stats<<<256, 256>>>();
    k_normpool<<<256, 256>>>(gamma, beta, batch);
    k_out<<<(GGx + 7) / 8, 256>>>(Wout, bout, out);
}